// round 12
// baseline (speedup 1.0000x reference)
#include <cuda_runtime.h>
#include <math.h>

#define EMB   512
#define HDIM  512
#define SEQ   2048
#define NENT  256
#define KTOK  8
#define G4H   2048   // 4*HDIM

#define NCTA  64     // CTAs per direction in the recurrence kernel
#define JPC   8      // h-indices owned per CTA (one per warp)

#define SENTINEL_U 0x7F800001u   // NaN pattern; h = o*tanh(c) is never NaN

// ---------------- scratch (device globals; no allocation allowed) ----------
__device__ float g_xproj[2][SEQ][G4H];   // 32 MB: x @ W_ih.T + b
// h history AND exchange medium: plain float array, each 4B store is atomic;
// validity of an element = (bits != SENTINEL_U).
__device__ __align__(16) float g_hx[2][SEQ][HDIM];   // 8 MB

__device__ __forceinline__ float fast_sigmoid(float x) {
    return __fdividef(1.f, 1.f + __expf(-x));
}
__device__ __forceinline__ float fast_tanh(float x) {
    return __fdividef(2.f, 1.f + __expf(-2.f * x)) - 1.f;
}

// relaxed GPU-scope v4 snapshot load (spin-poll safe via asm volatile)
#define POLL_LD(dst, p)                                                     \
    asm volatile("ld.relaxed.gpu.global.v4.f32 {%0,%1,%2,%3}, [%4];"        \
                 : "=f"((dst).x), "=f"((dst).y), "=f"((dst).z), "=f"((dst).w) \
                 : "l"(p) : "memory")

__device__ __forceinline__ bool pkt_ok(const float4& v) {
    return __float_as_uint(v.x) != SENTINEL_U &&
           __float_as_uint(v.y) != SENTINEL_U &&
           __float_as_uint(v.z) != SENTINEL_U &&
           __float_as_uint(v.w) != SENTINEL_U;
}

// ===========================================================================
// Kernel 1: fused embedding gather + x_proj GEMM (+bias), both directions.
// Also sentinel-clears ALL of g_hx.
// ===========================================================================
__global__ __launch_bounds__(256) void xproj_kernel(
    const float* __restrict__ emb_table,
    const int*   __restrict__ token_ids,
    const float* __restrict__ W_ih_f, const float* __restrict__ b_f,
    const float* __restrict__ W_ih_b, const float* __restrict__ b_b)
{
    __shared__ int   tok[64];
    __shared__ float As[16][68];
    __shared__ float Bs[16][68];

    const int tid = threadIdx.x;
    const int t0  = blockIdx.x * 64;
    const int r0  = blockIdx.y * 64;
    const int d   = blockIdx.z;

    // sentinel-clear the FULL g_hx array (2,097,152 floats = 524,288 float4)
    if (blockIdx.z == 0 && blockIdx.y < 16) {
        const float s = __uint_as_float(SENTINEL_U);
        float4 sv = make_float4(s, s, s, s);
        size_t lin = ((size_t)(blockIdx.y * 32 + blockIdx.x) * 256 + tid) * 4;
        float4* flat = (float4*)&g_hx[0][0][0];
        flat[lin]     = sv;
        flat[lin + 1] = sv;
        flat[lin + 2] = sv;
        flat[lin + 3] = sv;
    }

    if (tid < 64) tok[tid] = token_ids[t0 + tid];
    __syncthreads();

    const float* __restrict__ Wih  = d ? W_ih_b : W_ih_f;
    const float* __restrict__ bias = d ? b_b    : b_f;

    float acc[4][4];
    #pragma unroll
    for (int i = 0; i < 4; i++)
        #pragma unroll
        for (int j = 0; j < 4; j++) acc[i][j] = 0.f;

    const int lrow = tid >> 2;
    const int e4   = tid & 3;
    const int tx   = tid & 15;
    const int ty   = tid >> 4;

    const size_t arow = (size_t)tok[lrow] * EMB;
    const size_t brow = (size_t)(r0 + lrow) * EMB;

    for (int k0 = 0; k0 < EMB; k0 += 16) {
        float4 av = *(const float4*)(emb_table + arow + k0 + e4 * 4);
        float4 bv = *(const float4*)(Wih       + brow + k0 + e4 * 4);
        __syncthreads();
        As[e4 * 4 + 0][lrow] = av.x; As[e4 * 4 + 1][lrow] = av.y;
        As[e4 * 4 + 2][lrow] = av.z; As[e4 * 4 + 3][lrow] = av.w;
        Bs[e4 * 4 + 0][lrow] = bv.x; Bs[e4 * 4 + 1][lrow] = bv.y;
        Bs[e4 * 4 + 2][lrow] = bv.z; Bs[e4 * 4 + 3][lrow] = bv.w;
        __syncthreads();
        #pragma unroll
        for (int kk = 0; kk < 16; kk++) {
            float4 a = *(const float4*)&As[kk][tx * 4];
            float4 b = *(const float4*)&Bs[kk][ty * 4];
            acc[0][0] = fmaf(a.x, b.x, acc[0][0]); acc[0][1] = fmaf(a.x, b.y, acc[0][1]);
            acc[0][2] = fmaf(a.x, b.z, acc[0][2]); acc[0][3] = fmaf(a.x, b.w, acc[0][3]);
            acc[1][0] = fmaf(a.y, b.x, acc[1][0]); acc[1][1] = fmaf(a.y, b.y, acc[1][1]);
            acc[1][2] = fmaf(a.y, b.z, acc[1][2]); acc[1][3] = fmaf(a.y, b.w, acc[1][3]);
            acc[2][0] = fmaf(a.z, b.x, acc[2][0]); acc[2][1] = fmaf(a.z, b.y, acc[2][1]);
            acc[2][2] = fmaf(a.z, b.z, acc[2][2]); acc[2][3] = fmaf(a.z, b.w, acc[2][3]);
            acc[3][0] = fmaf(a.w, b.x, acc[3][0]); acc[3][1] = fmaf(a.w, b.y, acc[3][1]);
            acc[3][2] = fmaf(a.w, b.z, acc[3][2]); acc[3][3] = fmaf(a.w, b.w, acc[3][3]);
        }
    }

    float4 b4 = *(const float4*)(bias + r0 + ty * 4);
    #pragma unroll
    for (int i = 0; i < 4; i++) {
        int t = t0 + tx * 4 + i;
        float4 o = make_float4(acc[i][0] + b4.x, acc[i][1] + b4.y,
                               acc[i][2] + b4.z, acc[i][3] + b4.w);
        *(float4*)&g_xproj[d][t][r0 + ty * 4] = o;
    }
}

// ===========================================================================
// Kernel 2: persistent bi-LSTM recurrence, 128 co-resident CTAs.
// Warp-per-j; depth-4 pipelined relaxed-gpu poll (sample every ~60 cyc);
// xp prefetched one step ahead; one barrier per step.
// ===========================================================================
__global__ __launch_bounds__(256) void lstm_kernel(
    const float* __restrict__ W_hh_f,
    const float* __restrict__ W_hh_b)
{
    const int tid = threadIdx.x;
    const int bx  = blockIdx.x;
    const int d   = bx >> 6;
    const int cb  = bx & 63;
    const int j0  = cb * JPC;

    const float* __restrict__ Whh = d ? W_hh_b : W_hh_f;

    const int w = tid >> 5;         // warp -> local j
    const int l = tid & 31;
    const int q = l >> 3;           // gate 0..3 (i,f,g,o)
    const int s = l & 7;            // 64-col segment
    const int j = j0 + w;
    const int grow = q * HDIM + j;

    // weights packed as f32x2 pairs: 16 x ulonglong2 = 64 floats
    const ulonglong2* wp = (const ulonglong2*)(Whh + (size_t)grow * HDIM + s * 64);
    ulonglong2 wr[16];
    #pragma unroll
    for (int i = 0; i < 16; i++) wr[i] = wp[i];

    __shared__ float hsm[8 * 68];   // pitched: col-chunk c at hsm[c*68]
    float c = 0.f;                  // cell state, live in lane 0 of each warp

    // prefetch xp for step 0
    float xp_next = 0.f;
    {
        const int tfirst = d ? (SEQ - 1) : 0;
        if (s == 0) xp_next = __ldg(&g_xproj[d][tfirst][q * HDIM + j]);
    }

    #pragma unroll 1
    for (int step = 0; step < SEQ; step++) {
        const int t = d ? (SEQ - 1 - step) : step;

        const float xp = xp_next;
        // issue next step's xp load NOW (~1 full step of slack)
        if (step + 1 < SEQ && s == 0) {
            const int tn = d ? (SEQ - 2 - step) : (step + 1);
            xp_next = __ldg(&g_xproj[d][tn][q * HDIM + j]);
        }

        if (step == 0) {
            for (int i = tid; i < 8 * 68; i += 256) hsm[i] = 0.f;
        } else if (tid < 128) {
            // depth-4 pipelined poll: 4 independent snapshots in flight,
            // check the oldest -> sampling period ~latency/4.
            const int tprev = d ? (t + 1) : (t - 1);
            const float* src = &g_hx[d][tprev][tid * 4];
            float4 r0, r1, r2, r3, v;
            POLL_LD(r0, src); POLL_LD(r1, src);
            POLL_LD(r2, src); POLL_LD(r3, src);
            for (;;) {
                if (pkt_ok(r0)) { v = r0; break; }
                r0 = r1; r1 = r2; r2 = r3;
                POLL_LD(r3, src);
            }
            *(float4*)&hsm[(tid >> 4) * 68 + ((tid * 4) & 63)] = v;
        }
        __syncthreads();   // the ONLY barrier per step

        // GEMV: 64 MACs per lane as 32 packed f32x2 FMAs, 2 indep chains
        unsigned long long acc0 = 0ull, acc1 = 0ull;
        const ulonglong2* h2 = (const ulonglong2*)&hsm[s * 68];
        #pragma unroll
        for (int i = 0; i < 16; i++) {
            ulonglong2 hv = h2[i];
            asm("fma.rn.f32x2 %0, %1, %2, %0;"
                : "+l"(acc0) : "l"(wr[i].x), "l"(hv.x));
            asm("fma.rn.f32x2 %0, %1, %2, %0;"
                : "+l"(acc1) : "l"(wr[i].y), "l"(hv.y));
        }
        float lo0, hi0, lo1, hi1;
        asm("mov.b64 {%0,%1}, %2;" : "=f"(lo0), "=f"(hi0) : "l"(acc0));
        asm("mov.b64 {%0,%1}, %2;" : "=f"(lo1), "=f"(hi1) : "l"(acc1));
        float a = (lo0 + hi0) + (lo1 + hi1);

        // reduce across the 8 segments (aligned 8-lane subsets)
        a += __shfl_xor_sync(0xffffffffu, a, 4);
        a += __shfl_xor_sync(0xffffffffu, a, 2);
        a += __shfl_xor_sync(0xffffffffu, a, 1);
        a += xp;   // full gate value on lanes s==0 (l = 0,8,16,24)

        // parallel activations: lanes 0/8/24 sigmoid, lane 16 tanh via
        // 2*sigmoid(2x)-1. Branchless.
        float arg = (q == 2) ? 2.f * a : a;
        float sg  = fast_sigmoid(arg);
        float act = (q == 2) ? 2.f * sg - 1.f : sg;

        float ig = __shfl_sync(0xffffffffu, act, 0);
        float fg = __shfl_sync(0xffffffffu, act, 8);
        float tg = __shfl_sync(0xffffffffu, act, 16);
        float og = __shfl_sync(0xffffffffu, act, 24);

        if (l == 0) {
            c = fg * c + ig * tg;
            float hv = og * fast_tanh(c);
            asm volatile("st.relaxed.gpu.global.f32 [%0], %1;"
                         :: "l"(&g_hx[d][t][j]), "f"(hv) : "memory");
        }
        // no trailing barrier: next-step hsm overwrites are gated by the
        // pollers' success, which requires every warp's publish (and hence
        // every warp's hsm reads) of this step.
    }
}

// ===========================================================================
// Kernel 3: per-entity attention pool (entity_seg == repeat(arange(256), 8)).
// ===========================================================================
__global__ __launch_bounds__(256) void entity_kernel(
    const float* __restrict__ w_attn,
    const float* __restrict__ b_attn,
    const int*   __restrict__ entity_pos,
    float*       __restrict__ out)
{
    __shared__ int   pos[8];
    __shared__ float ssm[8];
    __shared__ float wsm[8];

    const int e   = blockIdx.x;
    const int tid = threadIdx.x;

    if (tid < 8) pos[tid] = entity_pos[e * KTOK + tid];
    __syncthreads();

    const int warp = tid >> 5, lane = tid & 31;
    const int p = pos[warp];
    float a = 0.f;
    for (int cc = lane; cc < HDIM; cc += 32)
        a = fmaf(g_hx[0][p][cc], w_attn[cc], a);
    for (int cc = lane; cc < HDIM; cc += 32)
        a = fmaf(g_hx[1][p][cc], w_attn[HDIM + cc], a);
    #pragma unroll
    for (int o = 16; o > 0; o >>= 1) a += __shfl_xor_sync(0xffffffffu, a, o);
    if (lane == 0) ssm[warp] = a + b_attn[0];
    __syncthreads();

    if (tid == 0) {
        float m = ssm[0];
        #pragma unroll
        for (int k = 1; k < 8; k++) m = fmaxf(m, ssm[k]);
        float ex[8], den = 0.f;
        #pragma unroll
        for (int k = 0; k < 8; k++) { ex[k] = expf(ssm[k] - m); den += ex[k]; }
        #pragma unroll
        for (int k = 0; k < 8; k++) wsm[k] = ex[k] / den;
    }
    __syncthreads();

    const int half = tid >> 7;
    const int c4   = tid & 127;
    float4 acc = make_float4(0.f, 0.f, 0.f, 0.f);
    #pragma unroll
    for (int k = 0; k < 8; k++) {
        float wk = wsm[k];
        float4 v = ((const float4*)&g_hx[half][pos[k]][0])[c4];
        acc.x = fmaf(wk, v.x, acc.x);
        acc.y = fmaf(wk, v.y, acc.y);
        acc.z = fmaf(wk, v.z, acc.z);
        acc.w = fmaf(wk, v.w, acc.w);
    }
    ((float4*)(out + (size_t)e * (2 * HDIM) + half * HDIM))[c4] = acc;
}

// ===========================================================================
extern "C" void kernel_launch(void* const* d_in, const int* in_sizes, int n_in,
                              void* d_out, int out_size)
{
    const float* emb_table  = (const float*)d_in[0];
    const float* W_ih_f     = (const float*)d_in[1];
    const float* W_hh_f     = (const float*)d_in[2];
    const float* b_f        = (const float*)d_in[3];
    const float* W_ih_b     = (const float*)d_in[4];
    const float* W_hh_b     = (const float*)d_in[5];
    const float* b_b        = (const float*)d_in[6];
    const float* w_attn     = (const float*)d_in[7];
    const float* b_attn     = (const float*)d_in[8];
    const int*   token_ids  = (const int*)d_in[9];
    const int*   entity_pos = (const int*)d_in[10];
    // d_in[11] entity_seg: repeat(arange(NENT), KTOK) -> implicit

    xproj_kernel<<<dim3(32, 32, 2), 256>>>(emb_table, token_ids,
                                           W_ih_f, b_f, W_ih_b, b_b);
    lstm_kernel<<<2 * NCTA, 256>>>(W_hh_f, W_hh_b);
    entity_kernel<<<NENT, 256>>>(w_attn, b_attn, entity_pos, (float*)d_out);
}

// round 14
// speedup vs baseline: 1.3406x; 1.3406x over previous
#include <cuda_runtime.h>
#include <math.h>

#define EMB   512
#define HDIM  512
#define SEQ   2048
#define NENT  256
#define KTOK  8
#define G4H   2048   // 4*HDIM

#define NCTA  64     // CTAs per direction in the recurrence kernel
#define JPC   8      // h-indices owned per CTA (one per warp)

#define SENTINEL_U 0x7F800001u   // NaN pattern; h = o*tanh(c) is never NaN

// ---------------- scratch (device globals; no allocation allowed) ----------
__device__ float g_xproj[2][SEQ][G4H];   // 32 MB: x @ W_ih.T + b
// h history AND exchange medium: plain float array, each 4B store is atomic;
// validity of an element = (bits != SENTINEL_U).
__device__ __align__(16) float g_hx[2][SEQ][HDIM];   // 8 MB

__device__ __forceinline__ float fast_sigmoid(float x) {
    return __fdividef(1.f, 1.f + __expf(-x));
}
__device__ __forceinline__ float fast_tanh(float x) {
    return __fdividef(2.f, 1.f + __expf(-2.f * x)) - 1.f;
}

__device__ __forceinline__ bool pkt_ok(const float4& v) {
    return __float_as_uint(v.x) != SENTINEL_U &&
           __float_as_uint(v.y) != SENTINEL_U &&
           __float_as_uint(v.z) != SENTINEL_U &&
           __float_as_uint(v.w) != SENTINEL_U;
}

// ===========================================================================
// Kernel 1: fused embedding gather + x_proj GEMM (+bias), both directions.
// Also sentinel-clears ALL of g_hx.
// ===========================================================================
__global__ __launch_bounds__(256) void xproj_kernel(
    const float* __restrict__ emb_table,
    const int*   __restrict__ token_ids,
    const float* __restrict__ W_ih_f, const float* __restrict__ b_f,
    const float* __restrict__ W_ih_b, const float* __restrict__ b_b)
{
    __shared__ int   tok[64];
    __shared__ float As[16][68];
    __shared__ float Bs[16][68];

    const int tid = threadIdx.x;
    const int t0  = blockIdx.x * 64;
    const int r0  = blockIdx.y * 64;
    const int d   = blockIdx.z;

    // sentinel-clear the FULL g_hx array (2,097,152 floats = 524,288 float4)
    if (blockIdx.z == 0 && blockIdx.y < 16) {
        const float s = __uint_as_float(SENTINEL_U);
        float4 sv = make_float4(s, s, s, s);
        size_t lin = ((size_t)(blockIdx.y * 32 + blockIdx.x) * 256 + tid) * 4;
        float4* flat = (float4*)&g_hx[0][0][0];
        flat[lin]     = sv;
        flat[lin + 1] = sv;
        flat[lin + 2] = sv;
        flat[lin + 3] = sv;
    }

    if (tid < 64) tok[tid] = token_ids[t0 + tid];
    __syncthreads();

    const float* __restrict__ Wih  = d ? W_ih_b : W_ih_f;
    const float* __restrict__ bias = d ? b_b    : b_f;

    float acc[4][4];
    #pragma unroll
    for (int i = 0; i < 4; i++)
        #pragma unroll
        for (int j = 0; j < 4; j++) acc[i][j] = 0.f;

    const int lrow = tid >> 2;
    const int e4   = tid & 3;
    const int tx   = tid & 15;
    const int ty   = tid >> 4;

    const size_t arow = (size_t)tok[lrow] * EMB;
    const size_t brow = (size_t)(r0 + lrow) * EMB;

    for (int k0 = 0; k0 < EMB; k0 += 16) {
        float4 av = *(const float4*)(emb_table + arow + k0 + e4 * 4);
        float4 bv = *(const float4*)(Wih       + brow + k0 + e4 * 4);
        __syncthreads();
        As[e4 * 4 + 0][lrow] = av.x; As[e4 * 4 + 1][lrow] = av.y;
        As[e4 * 4 + 2][lrow] = av.z; As[e4 * 4 + 3][lrow] = av.w;
        Bs[e4 * 4 + 0][lrow] = bv.x; Bs[e4 * 4 + 1][lrow] = bv.y;
        Bs[e4 * 4 + 2][lrow] = bv.z; Bs[e4 * 4 + 3][lrow] = bv.w;
        __syncthreads();
        #pragma unroll
        for (int kk = 0; kk < 16; kk++) {
            float4 a = *(const float4*)&As[kk][tx * 4];
            float4 b = *(const float4*)&Bs[kk][ty * 4];
            acc[0][0] = fmaf(a.x, b.x, acc[0][0]); acc[0][1] = fmaf(a.x, b.y, acc[0][1]);
            acc[0][2] = fmaf(a.x, b.z, acc[0][2]); acc[0][3] = fmaf(a.x, b.w, acc[0][3]);
            acc[1][0] = fmaf(a.y, b.x, acc[1][0]); acc[1][1] = fmaf(a.y, b.y, acc[1][1]);
            acc[1][2] = fmaf(a.y, b.z, acc[1][2]); acc[1][3] = fmaf(a.y, b.w, acc[1][3]);
            acc[2][0] = fmaf(a.z, b.x, acc[2][0]); acc[2][1] = fmaf(a.z, b.y, acc[2][1]);
            acc[2][2] = fmaf(a.z, b.z, acc[2][2]); acc[2][3] = fmaf(a.z, b.w, acc[2][3]);
            acc[3][0] = fmaf(a.w, b.x, acc[3][0]); acc[3][1] = fmaf(a.w, b.y, acc[3][1]);
            acc[3][2] = fmaf(a.w, b.z, acc[3][2]); acc[3][3] = fmaf(a.w, b.w, acc[3][3]);
        }
    }

    float4 b4 = *(const float4*)(bias + r0 + ty * 4);
    #pragma unroll
    for (int i = 0; i < 4; i++) {
        int t = t0 + tx * 4 + i;
        float4 o = make_float4(acc[i][0] + b4.x, acc[i][1] + b4.y,
                               acc[i][2] + b4.z, acc[i][3] + b4.w);
        *(float4*)&g_xproj[d][t][r0 + ty * 4] = o;
    }
}

// ===========================================================================
// Kernel 2: persistent bi-LSTM recurrence, 128 co-resident CTAs.
// Warp-per-j; 64 pollers x one producer-CTA's 32B (2 x v4 volatile loads,
// dependent-loop self-throttled); xp prefetched one step ahead; 1 barrier.
// ===========================================================================
__global__ __launch_bounds__(256) void lstm_kernel(
    const float* __restrict__ W_hh_f,
    const float* __restrict__ W_hh_b)
{
    const int tid = threadIdx.x;
    const int bx  = blockIdx.x;
    const int d   = bx >> 6;
    const int cb  = bx & 63;
    const int j0  = cb * JPC;

    const float* __restrict__ Whh = d ? W_hh_b : W_hh_f;

    const int w = tid >> 5;         // warp -> local j
    const int l = tid & 31;
    const int q = l >> 3;           // gate 0..3 (i,f,g,o)
    const int s = l & 7;            // 64-col segment
    const int j = j0 + w;
    const int grow = q * HDIM + j;

    // weights packed as f32x2 pairs: 16 x ulonglong2 = 64 floats
    const ulonglong2* wp = (const ulonglong2*)(Whh + (size_t)grow * HDIM + s * 64);
    ulonglong2 wr[16];
    #pragma unroll
    for (int i = 0; i < 16; i++) wr[i] = wp[i];

    __shared__ float hsm[8 * 68];   // pitched: col-chunk c at hsm[c*68]
    float c = 0.f;                  // cell state, live in lane 0 of each warp

    // prefetch xp for step 0
    float xp_next = 0.f;
    {
        const int tfirst = d ? (SEQ - 1) : 0;
        if (s == 0) xp_next = __ldg(&g_xproj[d][tfirst][q * HDIM + j]);
    }

    #pragma unroll 1
    for (int step = 0; step < SEQ; step++) {
        const int t = d ? (SEQ - 1 - step) : step;

        const float xp = xp_next;
        // issue next step's xp load now (~1 full step of slack to cover it)
        if (step + 1 < SEQ && s == 0) {
            const int tn = d ? (SEQ - 2 - step) : (step + 1);
            xp_next = __ldg(&g_xproj[d][tn][q * HDIM + j]);
        }

        if (step == 0) {
            for (int i = tid; i < 8 * 68; i += 256) hsm[i] = 0.f;
        } else if (tid < 64) {
            // poller tid owns producer CTA tid's 8 floats (32B, one sector):
            // two independent volatile v4 loads per round, self-throttled.
            const int tprev = d ? (t + 1) : (t - 1);
            const float* src = &g_hx[d][tprev][tid * 8];
            float4 va, vb;
            do {
                asm volatile("ld.volatile.global.v4.f32 {%0,%1,%2,%3}, [%4];"
                             : "=f"(va.x), "=f"(va.y), "=f"(va.z), "=f"(va.w)
                             : "l"(src) : "memory");
                asm volatile("ld.volatile.global.v4.f32 {%0,%1,%2,%3}, [%4];"
                             : "=f"(vb.x), "=f"(vb.y), "=f"(vb.z), "=f"(vb.w)
                             : "l"(src + 4) : "memory");
            } while (!pkt_ok(va) || !pkt_ok(vb));
            // 8 consecutive floats, aligned within one 64-col chunk
            float* hb = &hsm[(tid >> 3) * 68 + ((tid * 8) & 63)];
            ((float4*)hb)[0] = va;
            ((float4*)hb)[1] = vb;
        }
        __syncthreads();   // the ONLY barrier per step

        // GEMV: 64 MACs per lane as 32 packed f32x2 FMAs, 2 indep chains
        unsigned long long acc0 = 0ull, acc1 = 0ull;
        const ulonglong2* h2 = (const ulonglong2*)&hsm[s * 68];
        #pragma unroll
        for (int i = 0; i < 16; i++) {
            ulonglong2 hv = h2[i];
            asm("fma.rn.f32x2 %0, %1, %2, %0;"
                : "+l"(acc0) : "l"(wr[i].x), "l"(hv.x));
            asm("fma.rn.f32x2 %0, %1, %2, %0;"
                : "+l"(acc1) : "l"(wr[i].y), "l"(hv.y));
        }
        float lo0, hi0, lo1, hi1;
        asm("mov.b64 {%0,%1}, %2;" : "=f"(lo0), "=f"(hi0) : "l"(acc0));
        asm("mov.b64 {%0,%1}, %2;" : "=f"(lo1), "=f"(hi1) : "l"(acc1));
        float a = (lo0 + hi0) + (lo1 + hi1);

        // reduce across the 8 segments (aligned 8-lane subsets)
        a += __shfl_xor_sync(0xffffffffu, a, 4);
        a += __shfl_xor_sync(0xffffffffu, a, 2);
        a += __shfl_xor_sync(0xffffffffu, a, 1);
        a += xp;   // full gate value on lanes s==0 (l = 0,8,16,24)

        // parallel activations: lanes 0/8/24 sigmoid, lane 16 tanh via
        // 2*sigmoid(2x)-1. Branchless.
        float arg = (q == 2) ? 2.f * a : a;
        float sg  = fast_sigmoid(arg);
        float act = (q == 2) ? 2.f * sg - 1.f : sg;

        float ig = __shfl_sync(0xffffffffu, act, 0);
        float fg = __shfl_sync(0xffffffffu, act, 8);
        float tg = __shfl_sync(0xffffffffu, act, 16);
        float og = __shfl_sync(0xffffffffu, act, 24);

        if (l == 0) {
            c = fg * c + ig * tg;
            float hv = og * fast_tanh(c);
            asm volatile("st.relaxed.gpu.global.f32 [%0], %1;"
                         :: "l"(&g_hx[d][t][j]), "f"(hv) : "memory");
        }
        // no trailing barrier: next-step hsm overwrites are gated by the
        // pollers' success, which requires every warp's publish (and hence
        // every warp's hsm reads) of this step.
    }
}

// ===========================================================================
// Kernel 3: per-entity attention pool (entity_seg == repeat(arange(256), 8)).
// ===========================================================================
__global__ __launch_bounds__(256) void entity_kernel(
    const float* __restrict__ w_attn,
    const float* __restrict__ b_attn,
    const int*   __restrict__ entity_pos,
    float*       __restrict__ out)
{
    __shared__ int   pos[8];
    __shared__ float ssm[8];
    __shared__ float wsm[8];

    const int e   = blockIdx.x;
    const int tid = threadIdx.x;

    if (tid < 8) pos[tid] = entity_pos[e * KTOK + tid];
    __syncthreads();

    const int warp = tid >> 5, lane = tid & 31;
    const int p = pos[warp];
    float a = 0.f;
    for (int cc = lane; cc < HDIM; cc += 32)
        a = fmaf(g_hx[0][p][cc], w_attn[cc], a);
    for (int cc = lane; cc < HDIM; cc += 32)
        a = fmaf(g_hx[1][p][cc], w_attn[HDIM + cc], a);
    #pragma unroll
    for (int o = 16; o > 0; o >>= 1) a += __shfl_xor_sync(0xffffffffu, a, o);
    if (lane == 0) ssm[warp] = a + b_attn[0];
    __syncthreads();

    if (tid == 0) {
        float m = ssm[0];
        #pragma unroll
        for (int k = 1; k < 8; k++) m = fmaxf(m, ssm[k]);
        float ex[8], den = 0.f;
        #pragma unroll
        for (int k = 0; k < 8; k++) { ex[k] = expf(ssm[k] - m); den += ex[k]; }
        #pragma unroll
        for (int k = 0; k < 8; k++) wsm[k] = ex[k] / den;
    }
    __syncthreads();

    const int half = tid >> 7;
    const int c4   = tid & 127;
    float4 acc = make_float4(0.f, 0.f, 0.f, 0.f);
    #pragma unroll
    for (int k = 0; k < 8; k++) {
        float wk = wsm[k];
        float4 v = ((const float4*)&g_hx[half][pos[k]][0])[c4];
        acc.x = fmaf(wk, v.x, acc.x);
        acc.y = fmaf(wk, v.y, acc.y);
        acc.z = fmaf(wk, v.z, acc.z);
        acc.w = fmaf(wk, v.w, acc.w);
    }
    ((float4*)(out + (size_t)e * (2 * HDIM) + half * HDIM))[c4] = acc;
}

// ===========================================================================
extern "C" void kernel_launch(void* const* d_in, const int* in_sizes, int n_in,
                              void* d_out, int out_size)
{
    const float* emb_table  = (const float*)d_in[0];
    const float* W_ih_f     = (const float*)d_in[1];
    const float* W_hh_f     = (const float*)d_in[2];
    const float* b_f        = (const float*)d_in[3];
    const float* W_ih_b     = (const float*)d_in[4];
    const float* W_hh_b     = (const float*)d_in[5];
    const float* b_b        = (const float*)d_in[6];
    const float* w_attn     = (const float*)d_in[7];
    const float* b_attn     = (const float*)d_in[8];
    const int*   token_ids  = (const int*)d_in[9];
    const int*   entity_pos = (const int*)d_in[10];
    // d_in[11] entity_seg: repeat(arange(NENT), KTOK) -> implicit

    xproj_kernel<<<dim3(32, 32, 2), 256>>>(emb_table, token_ids,
                                           W_ih_f, b_f, W_ih_b, b_b);
    lstm_kernel<<<2 * NCTA, 256>>>(W_hh_f, W_hh_b);
    entity_kernel<<<NENT, 256>>>(w_attn, b_attn, entity_pos, (float*)d_out);
}

// round 15
// speedup vs baseline: 3.7380x; 2.7883x over previous
#include <cuda_runtime.h>
#include <math.h>

#define EMB   512
#define HDIM  512
#define SEQ   2048
#define NENT  256
#define KTOK  8
#define G4H   2048   // 4*HDIM

#define NCTA  64     // CTAs per direction in the recurrence kernel
#define JPC   8      // h-indices owned per CTA (one per warp)

#define SENTINEL_U 0x7F800001u   // NaN pattern; h = o*tanh(c) is never NaN

// ---------------- scratch (device globals; no allocation allowed) ----------
__device__ float g_xproj[2][SEQ][G4H];   // 32 MB: x @ W_ih.T + b
// h history AND exchange medium: plain float array, each 4B store is atomic;
// validity of an element = (bits != SENTINEL_U).
__device__ __align__(16) float g_hx[2][SEQ][HDIM];   // 8 MB

__device__ __forceinline__ float fast_sigmoid(float x) {
    return __fdividef(1.f, 1.f + __expf(-x));
}
__device__ __forceinline__ float fast_tanh(float x) {
    return __fdividef(2.f, 1.f + __expf(-2.f * x)) - 1.f;
}

__device__ __forceinline__ bool pkt_ok(const float4& v) {
    return __float_as_uint(v.x) != SENTINEL_U &&
           __float_as_uint(v.y) != SENTINEL_U &&
           __float_as_uint(v.z) != SENTINEL_U &&
           __float_as_uint(v.w) != SENTINEL_U;
}

// ===========================================================================
// Kernel 1: fused embedding gather + x_proj GEMM (+bias), both directions.
// 64(t) x 128(r) tile, 4x8 micro-tile (32 FMA per 3 LDS.128).
// Also sentinel-clears ALL of g_hx.
// Grid: x = 32 (t tiles), y = 16 (r tiles), z = 2 (direction).
// ===========================================================================
__global__ __launch_bounds__(256) void xproj_kernel(
    const float* __restrict__ emb_table,
    const int*   __restrict__ token_ids,
    const float* __restrict__ W_ih_f, const float* __restrict__ b_f,
    const float* __restrict__ W_ih_b, const float* __restrict__ b_b)
{
    __shared__ int   tok[64];
    __shared__ float As[16][68];    // [k][t], 64 t + pad
    __shared__ float Bs[16][132];   // [k][r], 128 r + pad

    const int tid = threadIdx.x;
    const int t0  = blockIdx.x * 64;
    const int r0  = blockIdx.y * 128;
    const int d   = blockIdx.z;

    // sentinel-clear the FULL g_hx array: all 512 z==0 blocks x 256 thr x 4 f4
    if (blockIdx.z == 0) {
        const float s = __uint_as_float(SENTINEL_U);
        float4 sv = make_float4(s, s, s, s);
        size_t lin = ((size_t)(blockIdx.y * 32 + blockIdx.x) * 256 + tid) * 4;
        float4* flat = (float4*)&g_hx[0][0][0];
        flat[lin]     = sv;
        flat[lin + 1] = sv;
        flat[lin + 2] = sv;
        flat[lin + 3] = sv;
    }

    if (tid < 64) tok[tid] = token_ids[t0 + tid];
    __syncthreads();

    const float* __restrict__ Wih  = d ? W_ih_b : W_ih_f;
    const float* __restrict__ bias = d ? b_b    : b_f;

    float acc[4][8];
    #pragma unroll
    for (int i = 0; i < 4; i++)
        #pragma unroll
        for (int jj = 0; jj < 8; jj++) acc[i][jj] = 0.f;

    // A loader: 64 rows x 16 k = 256 float4, one per thread
    const int alrow = tid >> 2;          // 0..63 (t)
    const int ae4   = tid & 3;           // float4 index within 16-wide chunk
    // B loader: 128 rows x 16 k = 512 float4, two per thread
    const int blrow = tid >> 1;          // 0..127 (r)
    const int be8   = (tid & 1) * 8;     // k offset {0, 8}

    const int tx = tid & 15;             // t micro (4 rows)
    const int ty = tid >> 4;             // r micro (8 cols)

    const size_t arow = (size_t)tok[alrow] * EMB;
    const size_t brow = (size_t)(r0 + blrow) * EMB;

    for (int k0 = 0; k0 < EMB; k0 += 16) {
        float4 av  = *(const float4*)(emb_table + arow + k0 + ae4 * 4);
        float4 bv0 = *(const float4*)(Wih       + brow + k0 + be8);
        float4 bv1 = *(const float4*)(Wih       + brow + k0 + be8 + 4);
        __syncthreads();   // previous chunk fully consumed
        As[ae4 * 4 + 0][alrow] = av.x; As[ae4 * 4 + 1][alrow] = av.y;
        As[ae4 * 4 + 2][alrow] = av.z; As[ae4 * 4 + 3][alrow] = av.w;
        Bs[be8 + 0][blrow] = bv0.x; Bs[be8 + 1][blrow] = bv0.y;
        Bs[be8 + 2][blrow] = bv0.z; Bs[be8 + 3][blrow] = bv0.w;
        Bs[be8 + 4][blrow] = bv1.x; Bs[be8 + 5][blrow] = bv1.y;
        Bs[be8 + 6][blrow] = bv1.z; Bs[be8 + 7][blrow] = bv1.w;
        __syncthreads();
        #pragma unroll
        for (int kk = 0; kk < 16; kk++) {
            float4 a  = *(const float4*)&As[kk][tx * 4];
            float4 b0 = *(const float4*)&Bs[kk][ty * 8];
            float4 b1 = *(const float4*)&Bs[kk][ty * 8 + 4];
            acc[0][0] = fmaf(a.x, b0.x, acc[0][0]); acc[0][1] = fmaf(a.x, b0.y, acc[0][1]);
            acc[0][2] = fmaf(a.x, b0.z, acc[0][2]); acc[0][3] = fmaf(a.x, b0.w, acc[0][3]);
            acc[0][4] = fmaf(a.x, b1.x, acc[0][4]); acc[0][5] = fmaf(a.x, b1.y, acc[0][5]);
            acc[0][6] = fmaf(a.x, b1.z, acc[0][6]); acc[0][7] = fmaf(a.x, b1.w, acc[0][7]);
            acc[1][0] = fmaf(a.y, b0.x, acc[1][0]); acc[1][1] = fmaf(a.y, b0.y, acc[1][1]);
            acc[1][2] = fmaf(a.y, b0.z, acc[1][2]); acc[1][3] = fmaf(a.y, b0.w, acc[1][3]);
            acc[1][4] = fmaf(a.y, b1.x, acc[1][4]); acc[1][5] = fmaf(a.y, b1.y, acc[1][5]);
            acc[1][6] = fmaf(a.y, b1.z, acc[1][6]); acc[1][7] = fmaf(a.y, b1.w, acc[1][7]);
            acc[2][0] = fmaf(a.z, b0.x, acc[2][0]); acc[2][1] = fmaf(a.z, b0.y, acc[2][1]);
            acc[2][2] = fmaf(a.z, b0.z, acc[2][2]); acc[2][3] = fmaf(a.z, b0.w, acc[2][3]);
            acc[2][4] = fmaf(a.z, b1.x, acc[2][4]); acc[2][5] = fmaf(a.z, b1.y, acc[2][5]);
            acc[2][6] = fmaf(a.z, b1.z, acc[2][6]); acc[2][7] = fmaf(a.z, b1.w, acc[2][7]);
            acc[3][0] = fmaf(a.w, b0.x, acc[3][0]); acc[3][1] = fmaf(a.w, b0.y, acc[3][1]);
            acc[3][2] = fmaf(a.w, b0.z, acc[3][2]); acc[3][3] = fmaf(a.w, b0.w, acc[3][3]);
            acc[3][4] = fmaf(a.w, b1.x, acc[3][4]); acc[3][5] = fmaf(a.w, b1.y, acc[3][5]);
            acc[3][6] = fmaf(a.w, b1.z, acc[3][6]); acc[3][7] = fmaf(a.w, b1.w, acc[3][7]);
        }
    }

    float4 bA = *(const float4*)(bias + r0 + ty * 8);
    float4 bB = *(const float4*)(bias + r0 + ty * 8 + 4);
    #pragma unroll
    for (int i = 0; i < 4; i++) {
        int t = t0 + tx * 4 + i;
        float4 o0 = make_float4(acc[i][0] + bA.x, acc[i][1] + bA.y,
                                acc[i][2] + bA.z, acc[i][3] + bA.w);
        float4 o1 = make_float4(acc[i][4] + bB.x, acc[i][5] + bB.y,
                                acc[i][6] + bB.z, acc[i][7] + bB.w);
        *(float4*)&g_xproj[d][t][r0 + ty * 8]     = o0;
        *(float4*)&g_xproj[d][t][r0 + ty * 8 + 4] = o1;
    }
}

// ===========================================================================
// Kernel 2: persistent bi-LSTM recurrence, 128 co-resident CTAs.
// BYTE-IDENTICAL to the 2861us version: warp-per-j; 128 pollers x one
// dependent volatile v4; f32x2 GEMV; parallel activations; one barrier.
// ===========================================================================
__global__ __launch_bounds__(256) void lstm_kernel(
    const float* __restrict__ W_hh_f,
    const float* __restrict__ W_hh_b)
{
    const int tid = threadIdx.x;
    const int bx  = blockIdx.x;
    const int d   = bx >> 6;
    const int cb  = bx & 63;
    const int j0  = cb * JPC;

    const float* __restrict__ Whh = d ? W_hh_b : W_hh_f;

    const int w = tid >> 5;         // warp -> local j
    const int l = tid & 31;
    const int q = l >> 3;           // gate 0..3 (i,f,g,o)
    const int s = l & 7;            // 64-col segment
    const int j = j0 + w;
    const int grow = q * HDIM + j;

    // weights packed as f32x2 pairs: 16 x ulonglong2 = 64 floats
    const ulonglong2* wp = (const ulonglong2*)(Whh + (size_t)grow * HDIM + s * 64);
    ulonglong2 wr[16];
    #pragma unroll
    for (int i = 0; i < 16; i++) wr[i] = wp[i];

    __shared__ float hsm[8 * 68];   // pitched: col-chunk c at hsm[c*68]
    float c = 0.f;                  // cell state, live in lane 0 of each warp

    #pragma unroll 1
    for (int step = 0; step < SEQ; step++) {
        const int t = d ? (SEQ - 1 - step) : step;

        // xp: lanes s==0 (l = 0,8,16,24) load gate q's input for this j
        float xp = 0.f;
        if (s == 0) xp = __ldg(&g_xproj[d][t][q * HDIM + j]);

        if (step == 0) {
            for (int i = tid; i < 8 * 68; i += 256) hsm[i] = 0.f;
        } else if (tid < 128) {
            // 128 pollers, one float4 each: poll == data delivery
            const int tprev = d ? (t + 1) : (t - 1);
            const float* src = &g_hx[d][tprev][tid * 4];
            float4 v;
            for (;;) {
                asm volatile("ld.volatile.global.v4.f32 {%0,%1,%2,%3}, [%4];"
                             : "=f"(v.x), "=f"(v.y), "=f"(v.z), "=f"(v.w)
                             : "l"(src) : "memory");
                if (pkt_ok(v)) break;
            }
            *(float4*)&hsm[(tid >> 4) * 68 + ((tid * 4) & 63)] = v;
        }
        __syncthreads();   // the ONLY barrier per step

        // GEMV: 64 MACs per lane as 32 packed f32x2 FMAs, 2 indep chains
        unsigned long long acc0 = 0ull, acc1 = 0ull;
        const ulonglong2* h2 = (const ulonglong2*)&hsm[s * 68];
        #pragma unroll
        for (int i = 0; i < 16; i++) {
            ulonglong2 hv = h2[i];
            asm("fma.rn.f32x2 %0, %1, %2, %0;"
                : "+l"(acc0) : "l"(wr[i].x), "l"(hv.x));
            asm("fma.rn.f32x2 %0, %1, %2, %0;"
                : "+l"(acc1) : "l"(wr[i].y), "l"(hv.y));
        }
        float lo0, hi0, lo1, hi1;
        asm("mov.b64 {%0,%1}, %2;" : "=f"(lo0), "=f"(hi0) : "l"(acc0));
        asm("mov.b64 {%0,%1}, %2;" : "=f"(lo1), "=f"(hi1) : "l"(acc1));
        float a = (lo0 + hi0) + (lo1 + hi1);

        // reduce across the 8 segments (aligned 8-lane subsets)
        a += __shfl_xor_sync(0xffffffffu, a, 4);
        a += __shfl_xor_sync(0xffffffffu, a, 2);
        a += __shfl_xor_sync(0xffffffffu, a, 1);
        a += xp;   // full gate value on lanes s==0 (l = 0,8,16,24)

        // parallel activations: lanes 0/8/24 sigmoid, lane 16 tanh via
        // 2*sigmoid(2x)-1. Branchless.
        float arg = (q == 2) ? 2.f * a : a;
        float sg  = fast_sigmoid(arg);
        float act = (q == 2) ? 2.f * sg - 1.f : sg;

        float ig = __shfl_sync(0xffffffffu, act, 0);
        float fg = __shfl_sync(0xffffffffu, act, 8);
        float tg = __shfl_sync(0xffffffffu, act, 16);
        float og = __shfl_sync(0xffffffffu, act, 24);

        if (l == 0) {
            c = fg * c + ig * tg;
            float hv = og * fast_tanh(c);
            asm volatile("st.relaxed.gpu.global.f32 [%0], %1;"
                         :: "l"(&g_hx[d][t][j]), "f"(hv) : "memory");
        }
        // no trailing barrier: next-step hsm overwrites are gated by the
        // pollers' success, which requires every warp's publish (and hence
        // every warp's hsm reads) of this step.
    }
}

// ===========================================================================
// Kernel 3: per-entity attention pool (entity_seg == repeat(arange(256), 8)).
// ===========================================================================
__global__ __launch_bounds__(256) void entity_kernel(
    const float* __restrict__ w_attn,
    const float* __restrict__ b_attn,
    const int*   __restrict__ entity_pos,
    float*       __restrict__ out)
{
    __shared__ int   pos[8];
    __shared__ float ssm[8];
    __shared__ float wsm[8];

    const int e   = blockIdx.x;
    const int tid = threadIdx.x;

    if (tid < 8) pos[tid] = entity_pos[e * KTOK + tid];
    __syncthreads();

    const int warp = tid >> 5, lane = tid & 31;
    const int p = pos[warp];
    float a = 0.f;
    for (int cc = lane; cc < HDIM; cc += 32)
        a = fmaf(g_hx[0][p][cc], w_attn[cc], a);
    for (int cc = lane; cc < HDIM; cc += 32)
        a = fmaf(g_hx[1][p][cc], w_attn[HDIM + cc], a);
    #pragma unroll
    for (int o = 16; o > 0; o >>= 1) a += __shfl_xor_sync(0xffffffffu, a, o);
    if (lane == 0) ssm[warp] = a + b_attn[0];
    __syncthreads();

    if (tid == 0) {
        float m = ssm[0];
        #pragma unroll
        for (int k = 1; k < 8; k++) m = fmaxf(m, ssm[k]);
        float ex[8], den = 0.f;
        #pragma unroll
        for (int k = 0; k < 8; k++) { ex[k] = expf(ssm[k] - m); den += ex[k]; }
        #pragma unroll
        for (int k = 0; k < 8; k++) wsm[k] = ex[k] / den;
    }
    __syncthreads();

    const int half = tid >> 7;
    const int c4   = tid & 127;
    float4 acc = make_float4(0.f, 0.f, 0.f, 0.f);
    #pragma unroll
    for (int k = 0; k < 8; k++) {
        float wk = wsm[k];
        float4 v = ((const float4*)&g_hx[half][pos[k]][0])[c4];
        acc.x = fmaf(wk, v.x, acc.x);
        acc.y = fmaf(wk, v.y, acc.y);
        acc.z = fmaf(wk, v.z, acc.z);
        acc.w = fmaf(wk, v.w, acc.w);
    }
    ((float4*)(out + (size_t)e * (2 * HDIM) + half * HDIM))[c4] = acc;
}

// ===========================================================================
extern "C" void kernel_launch(void* const* d_in, const int* in_sizes, int n_in,
                              void* d_out, int out_size)
{
    const float* emb_table  = (const float*)d_in[0];
    const float* W_ih_f     = (const float*)d_in[1];
    const float* W_hh_f     = (const float*)d_in[2];
    const float* b_f        = (const float*)d_in[3];
    const float* W_ih_b     = (const float*)d_in[4];
    const float* W_hh_b     = (const float*)d_in[5];
    const float* b_b        = (const float*)d_in[6];
    const float* w_attn     = (const float*)d_in[7];
    const float* b_attn     = (const float*)d_in[8];
    const int*   token_ids  = (const int*)d_in[9];
    const int*   entity_pos = (const int*)d_in[10];
    // d_in[11] entity_seg: repeat(arange(NENT), KTOK) -> implicit

    xproj_kernel<<<dim3(32, 16, 2), 256>>>(emb_table, token_ids,
                                           W_ih_f, b_f, W_ih_b, b_b);
    lstm_kernel<<<2 * NCTA, 256>>>(W_hh_f, W_hh_b);
    entity_kernel<<<NENT, 256>>>(w_attn, b_attn, entity_pos, (float*)d_out);
}